// round 1
// baseline (speedup 1.0000x reference)
#include <cuda_runtime.h>
#include <math.h>

#define NE 8
#define TOPK 2
#define DM 1024
#define DH 4096
#define T_TOK 4096
#define NPAIR (T_TOK*TOPK)

// ---------------- scratch (device globals; no allocation) ----------------
__device__ int   g_count[NE];
__device__ int   g_off[NE];
__device__ int   g_cursor[NE];
__device__ int   g_pair_tok[NPAIR];
__device__ float g_pair_w[NPAIR];
__device__ int   g_tok_e[T_TOK*TOPK];
__device__ float g_tok_w[T_TOK*TOPK];
__device__ float g_act[(size_t)NPAIR*DH];   // 128 MB: h*silu(g) per (token,expert) pair

// ---------------- reset: zero output + counters ----------------
__global__ void k_reset(float* out, int n) {
    int i = blockIdx.x*blockDim.x + threadIdx.x;
    if (i < n) out[i] = 0.f;
    if (i < NE) g_count[i] = 0;
}

// ---------------- routing: logits, top-2, softmax ----------------
__global__ void k_route(const float* __restrict__ x,
                        const float* __restrict__ Wg,
                        const float* __restrict__ bg) {
    int t = blockIdx.x;
    int tid = threadIdx.x;
    const float* xr = x + (size_t)t*DM;
    float acc[NE];
#pragma unroll
    for (int e = 0; e < NE; e++) acc[e] = 0.f;
    for (int i = tid; i < DM; i += 256) {
        float xv = xr[i];
#pragma unroll
        for (int e = 0; e < NE; e++) acc[e] += xv * Wg[i*NE + e];
    }
    __shared__ float s[NE][256];
#pragma unroll
    for (int e = 0; e < NE; e++) s[e][tid] = acc[e];
    __syncthreads();
    for (int off = 128; off > 0; off >>= 1) {
        if (tid < off) {
#pragma unroll
            for (int e = 0; e < NE; e++) s[e][tid] += s[e][tid + off];
        }
        __syncthreads();
    }
    if (tid == 0) {
        float v[NE];
#pragma unroll
        for (int e = 0; e < NE; e++) v[e] = s[e][0] + bg[e];
        // top-1: first occurrence of max (matches jax top_k tie-break)
        int i0 = 0;
#pragma unroll
        for (int e = 1; e < NE; e++) if (v[e] > v[i0]) i0 = e;
        // top-2: first occurrence of max among rest
        int i1 = (i0 == 0) ? 1 : 0;
#pragma unroll
        for (int e = 0; e < NE; e++) if (e != i0 && v[e] > v[i1]) i1 = e;
        float e1 = expf(v[i1] - v[i0]);       // v[i0] is max
        float inv = 1.f / (1.f + e1);
        g_tok_e[2*t]   = i0;  g_tok_w[2*t]   = inv;
        g_tok_e[2*t+1] = i1;  g_tok_w[2*t+1] = e1 * inv;
        atomicAdd(&g_count[i0], 1);
        atomicAdd(&g_count[i1], 1);
    }
}

// ---------------- exclusive scan of 8 counts ----------------
__global__ void k_scan() {
    int o = 0;
    for (int e = 0; e < NE; e++) {
        g_off[e] = o;
        g_cursor[e] = o;
        o += g_count[e];
    }
}

// ---------------- compact (token, weight) per expert ----------------
__global__ void k_assign() {
    int t = blockIdx.x*blockDim.x + threadIdx.x;
    if (t >= T_TOK) return;
#pragma unroll
    for (int k = 0; k < TOPK; k++) {
        int e = g_tok_e[2*t + k];
        int pos = atomicAdd(&g_cursor[e], 1);
        g_pair_tok[pos] = t;
        g_pair_w[pos]   = g_tok_w[2*t + k];
    }
}

// ---------------- pass A: act = (x@W0+b0) * silu(x@W1+b1), gathered grouped GEMM ----------------
// tile: 64(M) x 64(N) x 16(K), 256 threads, 4x4 microtile, dual-B (W0 & W1)
__global__ void __launch_bounds__(256) k_mlp1(const float* __restrict__ x,
                                              const float* __restrict__ W0,
                                              const float* __restrict__ b0,
                                              const float* __restrict__ W1,
                                              const float* __restrict__ b1) {
    int e   = blockIdx.z;
    int cnt = g_count[e];
    int m0  = blockIdx.y * 64;
    if (m0 >= cnt) return;
    int off = g_off[e];
    int n0  = blockIdx.x * 64;

    const float* B0 = W0 + (size_t)e*DM*DH;
    const float* B1 = W1 + (size_t)e*DM*DH;

    __shared__ float As [16][64];
    __shared__ float Bs0[16][64];
    __shared__ float Bs1[16][64];
    __shared__ int   toks[64];

    int tid = threadIdx.x;
    if (tid < 64) {
        int m = m0 + tid;
        toks[tid] = (m < cnt) ? g_pair_tok[off + m] : -1;
    }
    __syncthreads();

    int tx = tid % 16, ty = tid / 16;
    int kA = tid % 16, mA = tid / 16;   // A loader: 4 rows, stride 16
    int nB = tid % 64, kB = tid / 64;   // B loader: 4 k's, stride 4

    float acc_h[4][4], acc_g[4][4];
#pragma unroll
    for (int i = 0; i < 4; i++)
#pragma unroll
        for (int j = 0; j < 4; j++) { acc_h[i][j] = 0.f; acc_g[i][j] = 0.f; }

    for (int k0 = 0; k0 < DM; k0 += 16) {
#pragma unroll
        for (int i = 0; i < 4; i++) {
            int m = mA + i*16;
            int tok = toks[m];
            As[kA][m] = (tok >= 0) ? x[(size_t)tok*DM + k0 + kA] : 0.f;
        }
#pragma unroll
        for (int i = 0; i < 4; i++) {
            int k = kB + i*4;
            Bs0[k][nB] = B0[(size_t)(k0 + k)*DH + n0 + nB];
            Bs1[k][nB] = B1[(size_t)(k0 + k)*DH + n0 + nB];
        }
        __syncthreads();
#pragma unroll
        for (int kk = 0; kk < 16; kk++) {
            float4 av  = *(const float4*)&As [kk][ty*4];
            float4 b0v = *(const float4*)&Bs0[kk][tx*4];
            float4 b1v = *(const float4*)&Bs1[kk][tx*4];
            float a[4] = {av.x, av.y, av.z, av.w};
            float p[4] = {b0v.x, b0v.y, b0v.z, b0v.w};
            float q[4] = {b1v.x, b1v.y, b1v.z, b1v.w};
#pragma unroll
            for (int i = 0; i < 4; i++)
#pragma unroll
                for (int j = 0; j < 4; j++) {
                    acc_h[i][j] += a[i] * p[j];
                    acc_g[i][j] += a[i] * q[j];
                }
        }
        __syncthreads();
    }

    const float* b0p = b0 + (size_t)e*DH;
    const float* b1p = b1 + (size_t)e*DH;
#pragma unroll
    for (int i = 0; i < 4; i++) {
        int lm = ty*4 + i;
        if (m0 + lm < cnt) {
            size_t row = (size_t)(off + m0 + lm);
            int n = n0 + tx*4;
            float4 o;
            float h, g, sg;
            h = acc_h[i][0] + b0p[n+0]; g = acc_g[i][0] + b1p[n+0];
            sg = g / (1.f + expf(-g)); o.x = h * sg;
            h = acc_h[i][1] + b0p[n+1]; g = acc_g[i][1] + b1p[n+1];
            sg = g / (1.f + expf(-g)); o.y = h * sg;
            h = acc_h[i][2] + b0p[n+2]; g = acc_g[i][2] + b1p[n+2];
            sg = g / (1.f + expf(-g)); o.z = h * sg;
            h = acc_h[i][3] + b0p[n+3]; g = acc_g[i][3] + b1p[n+3];
            sg = g / (1.f + expf(-g)); o.w = h * sg;
            *(float4*)&g_act[row*DH + n] = o;
        }
    }
}

// ---------------- pass B: out[token] += w * (act @ W2 + b2) ----------------
__global__ void __launch_bounds__(256) k_mlp2(const float* __restrict__ W2,
                                              const float* __restrict__ b2,
                                              float* __restrict__ out) {
    int e   = blockIdx.z;
    int cnt = g_count[e];
    int m0  = blockIdx.y * 64;
    if (m0 >= cnt) return;
    int off = g_off[e];
    int n0  = blockIdx.x * 64;

    const float* B = W2 + (size_t)e*DH*DM;

    __shared__ float As[16][64];
    __shared__ float Bs[16][64];

    int tid = threadIdx.x;
    int tx = tid % 16, ty = tid / 16;
    int kA = tid % 16, mA = tid / 16;
    int nB = tid % 64, kB = tid / 64;

    float acc[4][4];
#pragma unroll
    for (int i = 0; i < 4; i++)
#pragma unroll
        for (int j = 0; j < 4; j++) acc[i][j] = 0.f;

    for (int k0 = 0; k0 < DH; k0 += 16) {
#pragma unroll
        for (int i = 0; i < 4; i++) {
            int m = mA + i*16;
            As[kA][m] = (m0 + m < cnt)
                ? g_act[(size_t)(off + m0 + m)*DH + k0 + kA] : 0.f;
        }
#pragma unroll
        for (int i = 0; i < 4; i++) {
            int k = kB + i*4;
            Bs[k][nB] = B[(size_t)(k0 + k)*DM + n0 + nB];
        }
        __syncthreads();
#pragma unroll
        for (int kk = 0; kk < 16; kk++) {
            float4 av = *(const float4*)&As[kk][ty*4];
            float4 bv = *(const float4*)&Bs[kk][tx*4];
            float a[4] = {av.x, av.y, av.z, av.w};
            float b[4] = {bv.x, bv.y, bv.z, bv.w};
#pragma unroll
            for (int i = 0; i < 4; i++)
#pragma unroll
                for (int j = 0; j < 4; j++) acc[i][j] += a[i] * b[j];
        }
        __syncthreads();
    }

    const float* b2p = b2 + (size_t)e*DM;
#pragma unroll
    for (int i = 0; i < 4; i++) {
        int lm = ty*4 + i;
        int m  = m0 + lm;
        if (m < cnt) {
            int tok = g_pair_tok[off + m];
            float w = g_pair_w[off + m];
            int n = n0 + tx*4;
            float* orow = out + (size_t)tok*DM;
#pragma unroll
            for (int j = 0; j < 4; j++) {
                atomicAdd(&orow[n + j], w * (acc[i][j] + b2p[n + j]));
            }
        }
    }
}

// ---------------- launch ----------------
extern "C" void kernel_launch(void* const* d_in, const int* in_sizes, int n_in,
                              void* d_out, int out_size) {
    const float* x  = (const float*)d_in[0];
    const float* Wg = (const float*)d_in[1];
    const float* bg = (const float*)d_in[2];
    const float* W0 = (const float*)d_in[3];
    const float* b0 = (const float*)d_in[4];
    const float* W1 = (const float*)d_in[5];
    const float* b1 = (const float*)d_in[6];
    const float* W2 = (const float*)d_in[7];
    const float* b2 = (const float*)d_in[8];
    float* out = (float*)d_out;

    k_reset <<<(T_TOK*DM + 255)/256, 256>>>(out, T_TOK*DM);
    k_route <<<T_TOK, 256>>>(x, Wg, bg);
    k_scan  <<<1, 1>>>();
    k_assign<<<(T_TOK + 255)/256, 256>>>();
    k_mlp1  <<<dim3(DH/64, T_TOK/64, NE), 256>>>(x, W0, b0, W1, b1);
    k_mlp2  <<<dim3(DM/64, T_TOK/64, NE), 256>>>(W2, b2, out);
}

// round 2
// speedup vs baseline: 2.9936x; 2.9936x over previous
#include <cuda_runtime.h>
#include <math.h>

#define NE 8
#define TOPK 2
#define DM 1024
#define DH 4096
#define T_TOK 4096
#define NPAIR (T_TOK*TOPK)
#define KS 32
#define ALD 136   // A smem row stride (words): conflict-free frag loads
#define BLD 72    // B smem row stride

// ---------------- scratch (device globals; no allocation) ----------------
__device__ int   g_count[NE];
__device__ int   g_off[NE];
__device__ int   g_cursor[NE];
__device__ int   g_pair_tok[NPAIR];
__device__ float g_pair_w[NPAIR];
__device__ int   g_tok_e[T_TOK*TOPK];
__device__ float g_tok_w[T_TOK*TOPK];
__device__ float g_act[(size_t)NPAIR*DH];   // 128 MB: h*silu(g) per (token,expert) pair

__device__ __forceinline__ unsigned f2tf(float f) {
    unsigned u;
    asm("cvt.rna.tf32.f32 %0, %1;" : "=r"(u) : "f"(f));
    return u;
}

__device__ __forceinline__ void mma_tf32(float c[4], const unsigned a[4],
                                         unsigned b0, unsigned b1) {
    asm volatile(
        "mma.sync.aligned.m16n8k8.row.col.f32.tf32.tf32.f32 "
        "{%0,%1,%2,%3}, {%4,%5,%6,%7}, {%8,%9}, {%0,%1,%2,%3};\n"
        : "+f"(c[0]), "+f"(c[1]), "+f"(c[2]), "+f"(c[3])
        : "r"(a[0]), "r"(a[1]), "r"(a[2]), "r"(a[3]), "r"(b0), "r"(b1));
}

// ---------------- reset: zero output + counters ----------------
__global__ void k_reset(float* out, int n) {
    int i = blockIdx.x*blockDim.x + threadIdx.x;
    if (i < n) out[i] = 0.f;
    if (i < NE) g_count[i] = 0;
}

// ---------------- routing: logits, top-2, softmax ----------------
__global__ void k_route(const float* __restrict__ x,
                        const float* __restrict__ Wg,
                        const float* __restrict__ bg) {
    int t = blockIdx.x;
    int tid = threadIdx.x;
    const float* xr = x + (size_t)t*DM;
    float acc[NE];
#pragma unroll
    for (int e = 0; e < NE; e++) acc[e] = 0.f;
    for (int i = tid; i < DM; i += 256) {
        float xv = xr[i];
#pragma unroll
        for (int e = 0; e < NE; e++) acc[e] += xv * Wg[i*NE + e];
    }
    __shared__ float s[NE][256];
#pragma unroll
    for (int e = 0; e < NE; e++) s[e][tid] = acc[e];
    __syncthreads();
    for (int off = 128; off > 0; off >>= 1) {
        if (tid < off) {
#pragma unroll
            for (int e = 0; e < NE; e++) s[e][tid] += s[e][tid + off];
        }
        __syncthreads();
    }
    if (tid == 0) {
        float v[NE];
#pragma unroll
        for (int e = 0; e < NE; e++) v[e] = s[e][0] + bg[e];
        int i0 = 0;
#pragma unroll
        for (int e = 1; e < NE; e++) if (v[e] > v[i0]) i0 = e;
        int i1 = (i0 == 0) ? 1 : 0;
#pragma unroll
        for (int e = 0; e < NE; e++) if (e != i0 && v[e] > v[i1]) i1 = e;
        float e1 = expf(v[i1] - v[i0]);
        float inv = 1.f / (1.f + e1);
        g_tok_e[2*t]   = i0;  g_tok_w[2*t]   = inv;
        g_tok_e[2*t+1] = i1;  g_tok_w[2*t+1] = e1 * inv;
        atomicAdd(&g_count[i0], 1);
        atomicAdd(&g_count[i1], 1);
    }
}

// ---------------- exclusive scan of 8 counts ----------------
__global__ void k_scan() {
    int o = 0;
    for (int e = 0; e < NE; e++) {
        g_off[e] = o;
        g_cursor[e] = o;
        o += g_count[e];
    }
}

// ---------------- compact (token, weight) per expert ----------------
__global__ void k_assign() {
    int t = blockIdx.x*blockDim.x + threadIdx.x;
    if (t >= T_TOK) return;
#pragma unroll
    for (int k = 0; k < TOPK; k++) {
        int e = g_tok_e[2*t + k];
        int pos = atomicAdd(&g_cursor[e], 1);
        g_pair_tok[pos] = t;
        g_pair_w[pos]   = g_tok_w[2*t + k];
    }
}

// ---------------- pass A: act = (x@W0+b0)*silu(x@W1+b1), tf32 mma ----------------
// block tile 128M x 64N, K-step 32. 8 warps (4M x 2N), warp tile 32x32 dual-B.
__global__ void __launch_bounds__(256) k_mlp1(const float* __restrict__ x,
                                              const float* __restrict__ W0,
                                              const float* __restrict__ b0,
                                              const float* __restrict__ W1,
                                              const float* __restrict__ b1) {
    int e   = blockIdx.z;
    int cnt = g_count[e];
    int m0  = blockIdx.y * 128;
    if (m0 >= cnt) return;
    int off = g_off[e];
    int n0  = blockIdx.x * 64;

    const float* B0g = W0 + (size_t)e*DM*DH;
    const float* B1g = W1 + (size_t)e*DM*DH;

    __shared__ unsigned As [KS][ALD];
    __shared__ unsigned Bs0[KS][BLD];
    __shared__ unsigned Bs1[KS][BLD];
    __shared__ int toks[128];

    int tid = threadIdx.x;
    if (tid < 128) {
        int m = m0 + tid;
        toks[tid] = (m < cnt) ? g_pair_tok[off + m] : -1;
    }
    __syncthreads();

    int lane = tid & 31, warp = tid >> 5;
    int wm = warp & 3, wn = warp >> 2;
    int g  = lane >> 2, tig = lane & 3;

    float ch[2][4][4], cg[2][4][4];
#pragma unroll
    for (int mi = 0; mi < 2; mi++)
#pragma unroll
        for (int ni = 0; ni < 4; ni++)
#pragma unroll
            for (int j = 0; j < 4; j++) { ch[mi][ni][j] = 0.f; cg[mi][ni][j] = 0.f; }

    int lm  = tid >> 1;          // A loader: row 0..127
    int lkh = (tid & 1) * 16;    // A loader: k half
    int bn  = (tid & 15) * 4;    // B loader: n
    int bk  = tid >> 4;          // B loader: k 0..15 (+16)
    int mytok = toks[lm];
    const float* xrow = (mytok >= 0) ? x + (size_t)mytok*DM + lkh : 0;

    for (int k0 = 0; k0 < DM; k0 += KS) {
        // --- A tile (transpose to [k][m], tf32) ---
        if (mytok >= 0) {
#pragma unroll
            for (int j = 0; j < 16; j += 4) {
                float4 v = *(const float4*)(xrow + k0 + j);
                As[lkh+j+0][lm] = f2tf(v.x);
                As[lkh+j+1][lm] = f2tf(v.y);
                As[lkh+j+2][lm] = f2tf(v.z);
                As[lkh+j+3][lm] = f2tf(v.w);
            }
        } else {
#pragma unroll
            for (int j = 0; j < 16; j++) As[lkh+j][lm] = 0u;
        }
        // --- B tiles ---
#pragma unroll
        for (int kk = 0; kk < 2; kk++) {
            int k = bk + kk*16;
            float4 v0 = *(const float4*)(B0g + (size_t)(k0 + k)*DH + n0 + bn);
            float4 v1 = *(const float4*)(B1g + (size_t)(k0 + k)*DH + n0 + bn);
            uint4 u0 = { f2tf(v0.x), f2tf(v0.y), f2tf(v0.z), f2tf(v0.w) };
            uint4 u1 = { f2tf(v1.x), f2tf(v1.y), f2tf(v1.z), f2tf(v1.w) };
            *(uint4*)&Bs0[k][bn] = u0;
            *(uint4*)&Bs1[k][bn] = u1;
        }
        __syncthreads();

#pragma unroll
        for (int ka = 0; ka < KS; ka += 8) {
            unsigned a[2][4];
#pragma unroll
            for (int mi = 0; mi < 2; mi++) {
                int m = wm*32 + mi*16 + g;
                a[mi][0] = As[ka+tig  ][m];
                a[mi][1] = As[ka+tig  ][m+8];
                a[mi][2] = As[ka+tig+4][m];
                a[mi][3] = As[ka+tig+4][m+8];
            }
#pragma unroll
            for (int ni = 0; ni < 4; ni++) {
                int n = wn*32 + ni*8 + g;
                unsigned b00 = Bs0[ka+tig][n], b01 = Bs0[ka+tig+4][n];
                unsigned b10 = Bs1[ka+tig][n], b11 = Bs1[ka+tig+4][n];
#pragma unroll
                for (int mi = 0; mi < 2; mi++) {
                    mma_tf32(ch[mi][ni], a[mi], b00, b01);
                    mma_tf32(cg[mi][ni], a[mi], b10, b11);
                }
            }
        }
        __syncthreads();
    }

    const float* b0p = b0 + (size_t)e*DH;
    const float* b1p = b1 + (size_t)e*DH;
#pragma unroll
    for (int mi = 0; mi < 2; mi++) {
#pragma unroll
        for (int hh = 0; hh < 2; hh++) {
            int r = m0 + wm*32 + mi*16 + g + hh*8;
            if (r < cnt) {
                size_t row = (size_t)(off + r);
#pragma unroll
                for (int ni = 0; ni < 4; ni++) {
                    int c = n0 + wn*32 + ni*8 + tig*2;
                    float h0 = ch[mi][ni][hh*2+0] + b0p[c];
                    float g0 = cg[mi][ni][hh*2+0] + b1p[c];
                    float h1 = ch[mi][ni][hh*2+1] + b0p[c+1];
                    float g1 = cg[mi][ni][hh*2+1] + b1p[c+1];
                    float2 o;
                    o.x = h0 * (g0 / (1.f + expf(-g0)));
                    o.y = h1 * (g1 / (1.f + expf(-g1)));
                    *(float2*)&g_act[row*DH + c] = o;
                }
            }
        }
    }
}

// ---------------- pass B: out[token] += w * (act @ W2 + b2), tf32 mma ----------------
__global__ void __launch_bounds__(256) k_mlp2(const float* __restrict__ W2,
                                              const float* __restrict__ b2,
                                              float* __restrict__ out) {
    int e   = blockIdx.z;
    int cnt = g_count[e];
    int m0  = blockIdx.y * 128;
    if (m0 >= cnt) return;
    int off = g_off[e];
    int n0  = blockIdx.x * 64;

    const float* Bg = W2 + (size_t)e*DH*DM;

    __shared__ unsigned As[KS][ALD];
    __shared__ unsigned Bs[KS][BLD];

    int tid = threadIdx.x;
    int lane = tid & 31, warp = tid >> 5;
    int wm = warp & 3, wn = warp >> 2;
    int g  = lane >> 2, tig = lane & 3;

    float acc[2][4][4];
#pragma unroll
    for (int mi = 0; mi < 2; mi++)
#pragma unroll
        for (int ni = 0; ni < 4; ni++)
#pragma unroll
            for (int j = 0; j < 4; j++) acc[mi][ni][j] = 0.f;

    int lm  = tid >> 1;
    int lkh = (tid & 1) * 16;
    int bn  = (tid & 15) * 4;
    int bk  = tid >> 4;
    int mrow = m0 + lm;
    const float* arow = (mrow < cnt) ? g_act + (size_t)(off + mrow)*DH + lkh : 0;

    for (int k0 = 0; k0 < DH; k0 += KS) {
        if (arow) {
#pragma unroll
            for (int j = 0; j < 16; j += 4) {
                float4 v = *(const float4*)(arow + k0 + j);
                As[lkh+j+0][lm] = f2tf(v.x);
                As[lkh+j+1][lm] = f2tf(v.y);
                As[lkh+j+2][lm] = f2tf(v.z);
                As[lkh+j+3][lm] = f2tf(v.w);
            }
        } else {
#pragma unroll
            for (int j = 0; j < 16; j++) As[lkh+j][lm] = 0u;
        }
#pragma unroll
        for (int kk = 0; kk < 2; kk++) {
            int k = bk + kk*16;
            float4 v = *(const float4*)(Bg + (size_t)(k0 + k)*DM + n0 + bn);
            uint4 u = { f2tf(v.x), f2tf(v.y), f2tf(v.z), f2tf(v.w) };
            *(uint4*)&Bs[k][bn] = u;
        }
        __syncthreads();

#pragma unroll
        for (int ka = 0; ka < KS; ka += 8) {
            unsigned a[2][4];
#pragma unroll
            for (int mi = 0; mi < 2; mi++) {
                int m = wm*32 + mi*16 + g;
                a[mi][0] = As[ka+tig  ][m];
                a[mi][1] = As[ka+tig  ][m+8];
                a[mi][2] = As[ka+tig+4][m];
                a[mi][3] = As[ka+tig+4][m+8];
            }
#pragma unroll
            for (int ni = 0; ni < 4; ni++) {
                int n = wn*32 + ni*8 + g;
                unsigned b0r = Bs[ka+tig][n], b1r = Bs[ka+tig+4][n];
#pragma unroll
                for (int mi = 0; mi < 2; mi++) {
                    mma_tf32(acc[mi][ni], a[mi], b0r, b1r);
                }
            }
        }
        __syncthreads();
    }

    const float* b2p = b2 + (size_t)e*DM;
#pragma unroll
    for (int mi = 0; mi < 2; mi++) {
#pragma unroll
        for (int hh = 0; hh < 2; hh++) {
            int r = m0 + wm*32 + mi*16 + g + hh*8;
            if (r < cnt) {
                int tok = g_pair_tok[off + r];
                float w = g_pair_w[off + r];
                float* orow = out + (size_t)tok*DM;
#pragma unroll
                for (int ni = 0; ni < 4; ni++) {
                    int c = n0 + wn*32 + ni*8 + tig*2;
                    atomicAdd(&orow[c],   w * (acc[mi][ni][hh*2+0] + b2p[c]));
                    atomicAdd(&orow[c+1], w * (acc[mi][ni][hh*2+1] + b2p[c+1]));
                }
            }
        }
    }
}

// ---------------- launch ----------------
extern "C" void kernel_launch(void* const* d_in, const int* in_sizes, int n_in,
                              void* d_out, int out_size) {
    const float* x  = (const float*)d_in[0];
    const float* Wg = (const float*)d_in[1];
    const float* bg = (const float*)d_in[2];
    const float* W0 = (const float*)d_in[3];
    const float* b0 = (const float*)d_in[4];
    const float* W1 = (const float*)d_in[5];
    const float* b1 = (const float*)d_in[6];
    const float* W2 = (const float*)d_in[7];
    const float* b2 = (const float*)d_in[8];
    float* out = (float*)d_out;

    k_reset <<<(T_TOK*DM + 255)/256, 256>>>(out, T_TOK*DM);
    k_route <<<T_TOK, 256>>>(x, Wg, bg);
    k_scan  <<<1, 1>>>();
    k_assign<<<(T_TOK + 255)/256, 256>>>();
    k_mlp1  <<<dim3(DH/64, 32, NE), 256>>>(x, W0, b0, W1, b1);
    k_mlp2  <<<dim3(DM/64, 32, NE), 256>>>(W2, b2, out);
}

// round 3
// speedup vs baseline: 4.1007x; 1.3698x over previous
#include <cuda_runtime.h>
#include <math.h>

#define NE 8
#define TOPK 2
#define DM 1024
#define DH 4096
#define T_TOK 4096
#define NPAIR (T_TOK*TOPK)
#define KS 32
#define ALD 36    // A smem row stride (words), [m][k] layout
#define BLD 72    // B smem row stride (words), [k][n] layout

// ---------------- scratch (device globals; no allocation) ----------------
__device__ int   g_count[NE];
__device__ int   g_off[NE];
__device__ int   g_cursor[NE];
__device__ int   g_pair_tok[NPAIR];
__device__ float g_pair_w[NPAIR];
__device__ int   g_tok_e[T_TOK*TOPK];
__device__ float g_tok_w[T_TOK*TOPK];
__device__ float g_act[(size_t)NPAIR*DH];          // 128 MB, stored pre-rounded to tf32
__device__ float g_w0[(size_t)NE*DM*DH];           // pre-rounded weights
__device__ float g_w1[(size_t)NE*DM*DH];
__device__ float g_w2[(size_t)NE*DH*DM];
__device__ float g_x[(size_t)T_TOK*DM];            // pre-rounded activations

__device__ __forceinline__ unsigned f2tf(float f) {
    unsigned u;
    asm("cvt.rna.tf32.f32 %0, %1;" : "=r"(u) : "f"(f));
    return u;
}

__device__ __forceinline__ void mma_tf32(float c[4], const unsigned a[4],
                                         unsigned b0, unsigned b1) {
    asm volatile(
        "mma.sync.aligned.m16n8k8.row.col.f32.tf32.tf32.f32 "
        "{%0,%1,%2,%3}, {%4,%5,%6,%7}, {%8,%9}, {%0,%1,%2,%3};\n"
        : "+f"(c[0]), "+f"(c[1]), "+f"(c[2]), "+f"(c[3])
        : "r"(a[0]), "r"(a[1]), "r"(a[2]), "r"(a[3]), "r"(b0), "r"(b1));
}

__device__ __forceinline__ unsigned sptr(const void* p) {
    return (unsigned)__cvta_generic_to_shared(p);
}
__device__ __forceinline__ void cp16(unsigned dst, const void* src, int srcbytes) {
    asm volatile("cp.async.cg.shared.global [%0], [%1], 16, %2;\n"
                 :: "r"(dst), "l"(src), "r"(srcbytes));
}
__device__ __forceinline__ void cp_commit() { asm volatile("cp.async.commit_group;\n"); }
__device__ __forceinline__ void cp_wait0()  { asm volatile("cp.async.wait_group 0;\n"); }

// ---------------- reset: zero output + counters ----------------
__global__ void k_reset(float* out, int n) {
    int i = blockIdx.x*blockDim.x + threadIdx.x;
    if (i < n) out[i] = 0.f;
    if (i < NE) g_count[i] = 0;
}

// ---------------- tf32 pre-round: out[i] = tf32(in[i]) ----------------
__global__ void k_cvt(const float* __restrict__ in, float* __restrict__ outp, int n4) {
    int i = blockIdx.x*blockDim.x + threadIdx.x;
    if (i < n4) {
        float4 v = ((const float4*)in)[i];
        v.x = __uint_as_float(f2tf(v.x));
        v.y = __uint_as_float(f2tf(v.y));
        v.z = __uint_as_float(f2tf(v.z));
        v.w = __uint_as_float(f2tf(v.w));
        ((float4*)outp)[i] = v;
    }
}

// ---------------- routing: logits, top-2, softmax ----------------
__global__ void k_route(const float* __restrict__ x,
                        const float* __restrict__ Wg,
                        const float* __restrict__ bg) {
    int t = blockIdx.x;
    int tid = threadIdx.x;
    const float* xr = x + (size_t)t*DM;
    float acc[NE];
#pragma unroll
    for (int e = 0; e < NE; e++) acc[e] = 0.f;
    for (int i = tid; i < DM; i += 256) {
        float xv = xr[i];
#pragma unroll
        for (int e = 0; e < NE; e++) acc[e] += xv * Wg[i*NE + e];
    }
    __shared__ float s[NE][256];
#pragma unroll
    for (int e = 0; e < NE; e++) s[e][tid] = acc[e];
    __syncthreads();
    for (int off = 128; off > 0; off >>= 1) {
        if (tid < off) {
#pragma unroll
            for (int e = 0; e < NE; e++) s[e][tid] += s[e][tid + off];
        }
        __syncthreads();
    }
    if (tid == 0) {
        float v[NE];
#pragma unroll
        for (int e = 0; e < NE; e++) v[e] = s[e][0] + bg[e];
        int i0 = 0;
#pragma unroll
        for (int e = 1; e < NE; e++) if (v[e] > v[i0]) i0 = e;
        int i1 = (i0 == 0) ? 1 : 0;
#pragma unroll
        for (int e = 0; e < NE; e++) if (e != i0 && v[e] > v[i1]) i1 = e;
        float e1 = expf(v[i1] - v[i0]);
        float inv = 1.f / (1.f + e1);
        g_tok_e[2*t]   = i0;  g_tok_w[2*t]   = inv;
        g_tok_e[2*t+1] = i1;  g_tok_w[2*t+1] = e1 * inv;
        atomicAdd(&g_count[i0], 1);
        atomicAdd(&g_count[i1], 1);
    }
}

// ---------------- exclusive scan of 8 counts ----------------
__global__ void k_scan() {
    int o = 0;
    for (int e = 0; e < NE; e++) {
        g_off[e] = o;
        g_cursor[e] = o;
        o += g_count[e];
    }
}

// ---------------- compact (token, weight) per expert ----------------
__global__ void k_assign() {
    int t = blockIdx.x*blockDim.x + threadIdx.x;
    if (t >= T_TOK) return;
#pragma unroll
    for (int k = 0; k < TOPK; k++) {
        int e = g_tok_e[2*t + k];
        int pos = atomicAdd(&g_cursor[e], 1);
        g_pair_tok[pos] = t;
        g_pair_w[pos]   = g_tok_w[2*t + k];
    }
}

// ================= pass A: act = (x@W0+b0)*silu(x@W1+b1) =================
// block 128M x 64N, KS=32, 2-stage cp.async pipeline, dual-B tf32 mma.
// dyn smem: As[2][128][36] + Bs0[2][32][72] + Bs1[2][32][72] + toks[128]
#define A1_WORDS (128*ALD)
#define B1_WORDS (KS*BLD)
__global__ void __launch_bounds__(256,2) k_mlp1(const float* __restrict__ b0,
                                                const float* __restrict__ b1) {
    int e   = blockIdx.z;
    int cnt = g_count[e];
    int m0  = blockIdx.y * 128;
    if (m0 >= cnt) return;
    int off = g_off[e];
    int n0  = blockIdx.x * 64;

    const float* B0g = g_w0 + (size_t)e*DM*DH;
    const float* B1g = g_w1 + (size_t)e*DM*DH;

    extern __shared__ float sm[];
    float* As  = sm;                          // [2][128][36]
    float* Bs0 = As + 2*A1_WORDS;             // [2][32][72]
    float* Bs1 = Bs0 + 2*B1_WORDS;            // [2][32][72]
    int*  toks = (int*)(Bs1 + 2*B1_WORDS);

    int tid = threadIdx.x;
    if (tid < 128) {
        int m = m0 + tid;
        toks[tid] = (m < cnt) ? g_pair_tok[off + m] : -1;
    }
    __syncthreads();

    // ---- loader precompute ----
    int akb  = tid & 7;                 // 16B chunk within row (8 per row of 32 floats)
    int arow = tid >> 3;                // base row (0..31), rows arow+32*i
    const float* asrc[4]; int asz[4]; unsigned adst[4];
#pragma unroll
    for (int i = 0; i < 4; i++) {
        int r = arow + 32*i;
        int tok = toks[r];
        asrc[i] = g_x + (size_t)(tok < 0 ? 0 : tok)*DM + akb*4;
        asz[i]  = (tok < 0) ? 0 : 16;
        adst[i] = sptr(As + r*ALD + akb*4);
    }
    int bnb = tid & 15;                 // 16B chunk in n (16 per row of 64 floats)
    int brow = tid >> 4;                // rows brow, brow+16
    const float* b0src0 = B0g + (size_t)brow*DH + n0 + bnb*4;
    const float* b1src0 = B1g + (size_t)brow*DH + n0 + bnb*4;
    unsigned b0dst0 = sptr(Bs0 + brow*BLD + bnb*4);
    unsigned b1dst0 = sptr(Bs1 + brow*BLD + bnb*4);

    int lane = tid & 31, warp = tid >> 5;
    int wm = warp & 3, wn = warp >> 2;
    int g  = lane >> 2, tig = lane & 3;

    float ch[2][4][4], cg[2][4][4];
#pragma unroll
    for (int mi = 0; mi < 2; mi++)
#pragma unroll
        for (int ni = 0; ni < 4; ni++)
#pragma unroll
            for (int j = 0; j < 4; j++) { ch[mi][ni][j] = 0.f; cg[mi][ni][j] = 0.f; }

    // ---- load stage helper (manually inlined twice) ----
#define LOAD_A1(stage, kk0)  {                                                        \
        unsigned soA = (stage)*A1_WORDS*4, soB = (stage)*B1_WORDS*4;                  \
        _Pragma("unroll")                                                             \
        for (int i = 0; i < 4; i++) cp16(adst[i] + soA, asrc[i] + (kk0), asz[i]);     \
        cp16(b0dst0 + soB, b0src0 + (size_t)(kk0)*DH, 16);                            \
        cp16(b0dst0 + soB + 16*BLD*4, b0src0 + (size_t)((kk0)+16)*DH, 16);            \
        cp16(b1dst0 + soB, b1src0 + (size_t)(kk0)*DH, 16);                            \
        cp16(b1dst0 + soB + 16*BLD*4, b1src0 + (size_t)((kk0)+16)*DH, 16);            \
        cp_commit(); }

    LOAD_A1(0, 0);

    const int NK = DM / KS;
    for (int kt = 0; kt < NK; kt++) {
        int cur = kt & 1;
        cp_wait0();
        __syncthreads();
        if (kt + 1 < NK) LOAD_A1(cur ^ 1, (kt + 1)*KS);

        const float* Ac  = As  + cur*A1_WORDS;
        const float* B0c = Bs0 + cur*B1_WORDS;
        const float* B1c = Bs1 + cur*B1_WORDS;
#pragma unroll
        for (int ka = 0; ka < KS; ka += 8) {
            unsigned a[2][4];
#pragma unroll
            for (int mi = 0; mi < 2; mi++) {
                int m = wm*32 + mi*16 + g;
                a[mi][0] = __float_as_uint(Ac[(m  )*ALD + ka + tig    ]);
                a[mi][1] = __float_as_uint(Ac[(m+8)*ALD + ka + tig    ]);
                a[mi][2] = __float_as_uint(Ac[(m  )*ALD + ka + tig + 4]);
                a[mi][3] = __float_as_uint(Ac[(m+8)*ALD + ka + tig + 4]);
            }
#pragma unroll
            for (int ni = 0; ni < 4; ni++) {
                int n = wn*32 + ni*8 + g;
                unsigned b00 = __float_as_uint(B0c[(ka+tig  )*BLD + n]);
                unsigned b01 = __float_as_uint(B0c[(ka+tig+4)*BLD + n]);
                unsigned b10 = __float_as_uint(B1c[(ka+tig  )*BLD + n]);
                unsigned b11 = __float_as_uint(B1c[(ka+tig+4)*BLD + n]);
#pragma unroll
                for (int mi = 0; mi < 2; mi++) {
                    mma_tf32(ch[mi][ni], a[mi], b00, b01);
                    mma_tf32(cg[mi][ni], a[mi], b10, b11);
                }
            }
        }
        __syncthreads();
    }

    const float* b0p = b0 + (size_t)e*DH;
    const float* b1p = b1 + (size_t)e*DH;
#pragma unroll
    for (int mi = 0; mi < 2; mi++) {
#pragma unroll
        for (int hh = 0; hh < 2; hh++) {
            int r = m0 + wm*32 + mi*16 + g + hh*8;
            if (r < cnt) {
                size_t row = (size_t)(off + r);
#pragma unroll
                for (int ni = 0; ni < 4; ni++) {
                    int c = n0 + wn*32 + ni*8 + tig*2;
                    float h0 = ch[mi][ni][hh*2+0] + b0p[c];
                    float g0 = cg[mi][ni][hh*2+0] + b1p[c];
                    float h1 = ch[mi][ni][hh*2+1] + b0p[c+1];
                    float g1 = cg[mi][ni][hh*2+1] + b1p[c+1];
                    float2 o;
                    o.x = __uint_as_float(f2tf(h0 * (g0 / (1.f + expf(-g0)))));
                    o.y = __uint_as_float(f2tf(h1 * (g1 / (1.f + expf(-g1)))));
                    *(float2*)&g_act[row*DH + c] = o;
                }
            }
        }
    }
}

// ================= pass B: out[token] += w * (act @ W2 + b2) =================
__global__ void __launch_bounds__(256,2) k_mlp2(const float* __restrict__ b2,
                                                float* __restrict__ out) {
    int e   = blockIdx.z;
    int cnt = g_count[e];
    int m0  = blockIdx.y * 128;
    if (m0 >= cnt) return;
    int off = g_off[e];
    int n0  = blockIdx.x * 64;

    const float* Bg = g_w2 + (size_t)e*DH*DM;

    extern __shared__ float sm[];
    float* As = sm;                 // [2][128][36]
    float* Bs = As + 2*A1_WORDS;    // [2][32][72]

    int tid = threadIdx.x;

    int akb  = tid & 7;
    int arow = tid >> 3;
    const float* asrc[4]; int asz[4]; unsigned adst[4];
#pragma unroll
    for (int i = 0; i < 4; i++) {
        int r = arow + 32*i;
        int m = m0 + r;
        int ok = (m < cnt);
        asrc[i] = g_act + (size_t)(ok ? (off + m) : 0)*DH + akb*4;
        asz[i]  = ok ? 16 : 0;
        adst[i] = sptr(As + r*ALD + akb*4);
    }
    int bnb = tid & 15;
    int brow = tid >> 4;
    const float* bsrc0 = Bg + (size_t)brow*DM + n0 + bnb*4;
    unsigned bdst0 = sptr(Bs + brow*BLD + bnb*4);

    int lane = tid & 31, warp = tid >> 5;
    int wm = warp & 3, wn = warp >> 2;
    int g  = lane >> 2, tig = lane & 3;

    float acc[2][4][4];
#pragma unroll
    for (int mi = 0; mi < 2; mi++)
#pragma unroll
        for (int ni = 0; ni < 4; ni++)
#pragma unroll
            for (int j = 0; j < 4; j++) acc[mi][ni][j] = 0.f;

#define LOAD_B1(stage, kk0)  {                                                        \
        unsigned soA = (stage)*A1_WORDS*4, soB = (stage)*B1_WORDS*4;                  \
        _Pragma("unroll")                                                             \
        for (int i = 0; i < 4; i++) cp16(adst[i] + soA, asrc[i] + (kk0), asz[i]);     \
        cp16(bdst0 + soB, bsrc0 + (size_t)(kk0)*DM, 16);                              \
        cp16(bdst0 + soB + 16*BLD*4, bsrc0 + (size_t)((kk0)+16)*DM, 16);              \
        cp_commit(); }

    LOAD_B1(0, 0);

    const int NK = DH / KS;
    for (int kt = 0; kt < NK; kt++) {
        int cur = kt & 1;
        cp_wait0();
        __syncthreads();
        if (kt + 1 < NK) LOAD_B1(cur ^ 1, (kt + 1)*KS);

        const float* Ac = As + cur*A1_WORDS;
        const float* Bc = Bs + cur*B1_WORDS;
#pragma unroll
        for (int ka = 0; ka < KS; ka += 8) {
            unsigned a[2][4];
#pragma unroll
            for (int mi = 0; mi < 2; mi++) {
                int m = wm*32 + mi*16 + g;
                a[mi][0] = __float_as_uint(Ac[(m  )*ALD + ka + tig    ]);
                a[mi][1] = __float_as_uint(Ac[(m+8)*ALD + ka + tig    ]);
                a[mi][2] = __float_as_uint(Ac[(m  )*ALD + ka + tig + 4]);
                a[mi][3] = __float_as_uint(Ac[(m+8)*ALD + ka + tig + 4]);
            }
#pragma unroll
            for (int ni = 0; ni < 4; ni++) {
                int n = wn*32 + ni*8 + g;
                unsigned b0r = __float_as_uint(Bc[(ka+tig  )*BLD + n]);
                unsigned b1r = __float_as_uint(Bc[(ka+tig+4)*BLD + n]);
#pragma unroll
                for (int mi = 0; mi < 2; mi++) {
                    mma_tf32(acc[mi][ni], a[mi], b0r, b1r);
                }
            }
        }
        __syncthreads();
    }

    const float* b2p = b2 + (size_t)e*DM;
#pragma unroll
    for (int mi = 0; mi < 2; mi++) {
#pragma unroll
        for (int hh = 0; hh < 2; hh++) {
            int r = m0 + wm*32 + mi*16 + g + hh*8;
            if (r < cnt) {
                int tok = g_pair_tok[off + r];
                float w = g_pair_w[off + r];
                float* orow = out + (size_t)tok*DM;
#pragma unroll
                for (int ni = 0; ni < 4; ni++) {
                    int c = n0 + wn*32 + ni*8 + tig*2;
                    atomicAdd(&orow[c],   w * (acc[mi][ni][hh*2+0] + b2p[c]));
                    atomicAdd(&orow[c+1], w * (acc[mi][ni][hh*2+1] + b2p[c+1]));
                }
            }
        }
    }
}

// ---------------- launch ----------------
#define SMEM_MLP1 ((2*A1_WORDS + 4*B1_WORDS)*4 + 128*4)
#define SMEM_MLP2 ((2*A1_WORDS + 2*B1_WORDS)*4)

extern "C" void kernel_launch(void* const* d_in, const int* in_sizes, int n_in,
                              void* d_out, int out_size) {
    const float* x  = (const float*)d_in[0];
    const float* Wg = (const float*)d_in[1];
    const float* bg = (const float*)d_in[2];
    const float* W0 = (const float*)d_in[3];
    const float* b0 = (const float*)d_in[4];
    const float* W1 = (const float*)d_in[5];
    const float* b1 = (const float*)d_in[6];
    const float* W2 = (const float*)d_in[7];
    const float* b2 = (const float*)d_in[8];
    float* out = (float*)d_out;

    static int smem_set = 0;
    if (!smem_set) {
        cudaFuncSetAttribute(k_mlp1, cudaFuncAttributeMaxDynamicSharedMemorySize, SMEM_MLP1);
        cudaFuncSetAttribute(k_mlp2, cudaFuncAttributeMaxDynamicSharedMemorySize, SMEM_MLP2);
        smem_set = 1;
    }

    float* w0d; cudaGetSymbolAddress((void**)&w0d, g_w0);
    float* w1d; cudaGetSymbolAddress((void**)&w1d, g_w1);
    float* w2d; cudaGetSymbolAddress((void**)&w2d, g_w2);
    float* xd;  cudaGetSymbolAddress((void**)&xd,  g_x);

    const int WN4 = NE*DM*DH/4;
    const int XN4 = T_TOK*DM/4;

    k_reset <<<(T_TOK*DM + 255)/256, 256>>>(out, T_TOK*DM);
    k_route <<<T_TOK, 256>>>(x, Wg, bg);
    k_scan  <<<1, 1>>>();
    k_assign<<<(T_TOK + 255)/256, 256>>>();
    k_cvt   <<<(WN4 + 255)/256, 256>>>(W0, w0d, WN4);
    k_cvt   <<<(WN4 + 255)/256, 256>>>(W1, w1d, WN4);
    k_cvt   <<<(WN4 + 255)/256, 256>>>(W2, w2d, WN4);
    k_cvt   <<<(XN4 + 255)/256, 256>>>(x,  xd,  XN4);
    k_mlp1  <<<dim3(DH/64, 32, NE), 256, SMEM_MLP1>>>(b0, b1);
    k_mlp2  <<<dim3(DM/64, 32, NE), 256, SMEM_MLP2>>>(b2, out);
}